// round 10
// baseline (speedup 1.0000x reference)
#include <cuda_runtime.h>
#include <cuda_bf16.h>
#include <cstdint>

#define B_   2048
#define T_   200
#define D_   128
#define H_   128
#define M_   (B_ * T_)          // 409600 rows

// ---------------- scratch (static device arrays; no allocation) ----------------
__device__ float g_Gx[(size_t)M_ * 256];   // x-part of gate pre-activations (NO bias)
__device__ float g_Cx[(size_t)M_ * 128];   // x-part of candidate pre-activations (NO bias)
__device__ int   g_perm[B_];
__device__ int   g_sls[B_];
// Full W^T hi/lo: [n (384)][k (256)].  k 0..127 = x-part, 128..255 = h-part
__device__ __align__(16) __nv_bfloat16 g_WThi[384 * 256];
__device__ __align__(16) __nv_bfloat16 g_WTlo[384 * 256];

// ---------------- math helpers ---------------------------------------------------
__device__ __forceinline__ float sigmoid_fast(float x) {
    float e;
    asm("ex2.approx.f32 %0, %1;" : "=f"(e) : "f"(-1.4426950408889634f * x));
    float r;
    asm("rcp.approx.f32 %0, %1;" : "=f"(r) : "f"(1.0f + e));
    return r;
}
__device__ __forceinline__ float tanh_fast(float x) {
    return fmaf(2.0f, sigmoid_fast(2.0f * x), -1.0f);
}
__device__ __forceinline__ uint32_t bf16pack(float a, float b) {
    __nv_bfloat16 ha = __float2bfloat16(a), hb = __float2bfloat16(b);
    return ((uint32_t)__bfloat16_as_ushort(hb) << 16) | __bfloat16_as_ushort(ha);
}
__device__ __forceinline__ float bflo(uint32_t v) {
    return __bfloat162float(__ushort_as_bfloat16((unsigned short)(v & 0xFFFF)));
}
__device__ __forceinline__ float bfhi(uint32_t v) {
    return __bfloat162float(__ushort_as_bfloat16((unsigned short)(v >> 16)));
}
__device__ __forceinline__ uint32_t bf16res(float a, float b, uint32_t hi) {
    return bf16pack(a - bflo(hi), b - bfhi(hi));
}
__device__ __forceinline__ uint32_t smem_u32(const void* p) {
    uint32_t a;
    asm("{ .reg .u64 t; cvta.to.shared.u64 t, %1; cvt.u32.u64 %0, t; }" : "=r"(a) : "l"(p));
    return a;
}

// ---------------- warp-level bf16 MMA (sm_80+, legal on compute_103) -------------
__device__ __forceinline__ void mma16816(float* c,
    uint32_t a0, uint32_t a1, uint32_t a2, uint32_t a3,
    uint32_t b0, uint32_t b1)
{
    asm volatile(
        "mma.sync.aligned.m16n8k16.row.col.f32.bf16.bf16.f32 "
        "{%0,%1,%2,%3}, {%4,%5,%6,%7}, {%8,%9}, {%0,%1,%2,%3};"
        : "+f"(c[0]), "+f"(c[1]), "+f"(c[2]), "+f"(c[3])
        : "r"(a0), "r"(a1), "r"(a2), "r"(a3), "r"(b0), "r"(b1));
}
__device__ __forceinline__ void cpasync16(uint32_t dst, const void* src) {
    asm volatile("cp.async.cg.shared.global [%0], [%1], 16;" :: "r"(dst), "l"(src));
}
#define CPASYNC_COMMIT() asm volatile("cp.async.commit_group;" ::: "memory")
#define CPASYNC_WAIT(N)  asm volatile("cp.async.wait_group %0;" :: "n"(N) : "memory")

// =============================================================================
// Kernel 0a: FULL W transpose + bf16 hi/lo split. WT[n][k] = W[k][n], k 0..255.
// =============================================================================
__global__ void __launch_bounds__(256) augru_wprep(
    const float* __restrict__ Wg, const float* __restrict__ Wc,
    __nv_bfloat16* __restrict__ WThi, __nv_bfloat16* __restrict__ WTlo)
{
    __shared__ float s[32][33];
    const int n0 = blockIdx.x * 32;
    const int tx = threadIdx.x & 31, ty = threadIdx.x >> 5;
    for (int k0 = 0; k0 < 256; k0 += 32) {
        for (int rr = 0; rr < 32; rr += 8) {
            int k = k0 + ty + rr, n = n0 + tx;
            s[ty + rr][tx] = (n0 < 256) ? Wg[(size_t)k * 256 + n]
                                        : Wc[(size_t)k * 128 + (n - 256)];
        }
        __syncthreads();
        for (int rr = 0; rr < 32; rr += 8) {
            int n = n0 + ty + rr, k = k0 + tx;
            float v = s[tx][ty + rr];
            __nv_bfloat16 hi = __float2bfloat16(v);
            float lo = v - __bfloat162float(hi);
            WThi[(size_t)n * 256 + k] = hi;
            WTlo[(size_t)n * 256 + k] = __float2bfloat16(lo);
        }
        __syncthreads();
    }
}

// =============================================================================
// Kernel 0b: parallel deterministic sort by seq_len, DESCENDING.
// =============================================================================
__global__ void __launch_bounds__(256) augru_sort(const int* __restrict__ seqlen,
                                                  int* __restrict__ perm,
                                                  int* __restrict__ sls)
{
    __shared__ int sl[B_];
    const int tid = threadIdx.x;
    for (int i = tid; i < B_; i += 256) sl[i] = seqlen[i];
    __syncthreads();
    const int b = blockIdx.x * 256 + tid;
    const int v = sl[b];
    int pos = 0;
#pragma unroll 8
    for (int j = 0; j < B_; j++) {
        int u = sl[j];
        pos += (u > v) || (u == v && j < b);
    }
    perm[pos] = b;
    sls[pos]  = v;
}

// =============================================================================
// Kernel 1: merged HMMA precompute (R9 version — X staged once, W double-
// buffered via cp.async overlapping MMA).
// =============================================================================
#define BSTR 136
#define QA_H 0
#define QA_L 34816
#define QB0  69632
#define QB1  139264
#define PC_SMEM 208896

__global__ void __launch_bounds__(256, 1) augru_precompute_mma(
    const float* __restrict__ X,
    const __nv_bfloat16* __restrict__ WThi,
    const __nv_bfloat16* __restrict__ WTlo,
    const int* __restrict__ seqlen,
    float* __restrict__ Gx, float* __restrict__ Cx)
{
    const int m0 = blockIdx.x * 128;
    {
        int b1 = m0 / T_;
        int t1 = m0 - b1 * T_;
        bool any = (t1 < seqlen[b1]);
        int b2 = (m0 + 127) / T_;
        if (b2 != b1) any = any || (seqlen[b2] > 0);
        if (!any) return;
    }

    extern __shared__ char smem[];
    const uint32_t sb = smem_u32(smem);
    const int tid = threadIdx.x;

    auto issueB = [&](int nt, uint32_t bufo) {
#pragma unroll
        for (int q = 0; q < 8; q++) {
            int f = q * 256 + tid;
            int n = f >> 4, c = f & 15;
            cpasync16(sb + bufo + n * 272 + c * 16,
                      &WThi[(size_t)(nt * 128 + n) * 256 + c * 8]);
        }
#pragma unroll
        for (int q = 0; q < 8; q++) {
            int f = q * 256 + tid;
            int n = f >> 4, c = f & 15;
            cpasync16(sb + bufo + 34816 + n * 272 + c * 16,
                      &WTlo[(size_t)(nt * 128 + n) * 256 + c * 8]);
        }
        CPASYNC_COMMIT();
    };

    issueB(0, QB0);

#pragma unroll
    for (int q = 0; q < 16; q++) {
        int f = q * 256 + tid;
        int m = f >> 5, k = (f & 31) << 2;
        float4 v = *(const float4*)&X[(size_t)(m0 + m) * 128 + k];
        __nv_bfloat16 h0 = __float2bfloat16(v.x), h1 = __float2bfloat16(v.y);
        __nv_bfloat16 h2 = __float2bfloat16(v.z), h3 = __float2bfloat16(v.w);
        uint32_t hv0 = ((uint32_t)__bfloat16_as_ushort(h1) << 16) | __bfloat16_as_ushort(h0);
        uint32_t hv1 = ((uint32_t)__bfloat16_as_ushort(h3) << 16) | __bfloat16_as_ushort(h2);
        uint32_t lv0 = bf16pack(v.x - __bfloat162float(h0), v.y - __bfloat162float(h1));
        uint32_t lv1 = bf16pack(v.z - __bfloat162float(h2), v.w - __bfloat162float(h3));
        size_t o = ((size_t)m * BSTR + k) * 2;
        *(uint32_t*)(smem + QA_H + o)     = hv0;
        *(uint32_t*)(smem + QA_H + o + 4) = hv1;
        *(uint32_t*)(smem + QA_L + o)     = lv0;
        *(uint32_t*)(smem + QA_L + o + 4) = lv1;
    }

    issueB(1, QB1);

    const int wid = tid >> 5, lane = tid & 31;
    const int wm = wid >> 2, wn = wid & 3;
    const int g = lane >> 2, tig = lane & 3;

    auto mmaNT = [&](int nt, uint32_t bufo) {
        float acc[4][4][4];
#pragma unroll
        for (int i = 0; i < 4; i++)
#pragma unroll
            for (int j = 0; j < 4; j++)
#pragma unroll
                for (int e = 0; e < 4; e++) acc[i][j][e] = 0.0f;

        const char* Bh = smem + bufo;
        const char* Bl = smem + bufo + 34816;
#pragma unroll 1
        for (int prod = 0; prod < 3; prod++) {
            const char* Ab = smem + ((prod == 1) ? QA_L : QA_H);
            const char* Bb = (prod == 2) ? Bl : Bh;
#pragma unroll
            for (int ks = 0; ks < 8; ks++) {
                const int k0 = ks * 16 + 2 * tig;
                uint32_t a[4][4], b[4][2];
#pragma unroll
                for (int ma = 0; ma < 4; ma++) {
                    int r0 = wm * 64 + ma * 16 + g;
                    a[ma][0] = *(const uint32_t*)(Ab + ((size_t)r0 * BSTR + k0) * 2);
                    a[ma][1] = *(const uint32_t*)(Ab + ((size_t)(r0 + 8) * BSTR + k0) * 2);
                    a[ma][2] = *(const uint32_t*)(Ab + ((size_t)r0 * BSTR + k0 + 8) * 2);
                    a[ma][3] = *(const uint32_t*)(Ab + ((size_t)(r0 + 8) * BSTR + k0 + 8) * 2);
                }
#pragma unroll
                for (int na = 0; na < 4; na++) {
                    int n0 = wn * 32 + na * 8 + g;
                    b[na][0] = *(const uint32_t*)(Bb + ((size_t)n0 * BSTR + k0) * 2);
                    b[na][1] = *(const uint32_t*)(Bb + ((size_t)n0 * BSTR + k0 + 8) * 2);
                }
#pragma unroll
                for (int ma = 0; ma < 4; ma++)
#pragma unroll
                    for (int na = 0; na < 4; na++)
                        mma16816(acc[ma][na], a[ma][0], a[ma][1], a[ma][2], a[ma][3],
                                 b[na][0], b[na][1]);
            }
        }
        float* Out = (nt < 2) ? Gx : Cx;
        const int ldo = (nt < 2) ? 256 : 128;
        const int nc0 = (nt < 2) ? nt * 128 : 0;
#pragma unroll
        for (int ma = 0; ma < 4; ma++) {
            int r = m0 + wm * 64 + ma * 16 + g;
#pragma unroll
            for (int na = 0; na < 4; na++) {
                int col = nc0 + wn * 32 + na * 8 + 2 * tig;
                *(float2*)&Out[(size_t)r * ldo + col] = make_float2(acc[ma][na][0], acc[ma][na][1]);
                *(float2*)&Out[(size_t)(r + 8) * ldo + col] = make_float2(acc[ma][na][2], acc[ma][na][3]);
            }
        }
    };

    CPASYNC_WAIT(1);
    __syncthreads();
    mmaNT(0, QB0);
    __syncthreads();
    issueB(2, QB0);
    CPASYNC_WAIT(1);
    __syncthreads();
    mmaNT(1, QB1);
    CPASYNC_WAIT(0);
    __syncthreads();
    mmaNT(2, QB0);
}

// =============================================================================
// Kernel 2: HMMA recurrence, R8 structure with 2 barriers/step.
//   U-warps (0-7):  update gate cols 128+[16w,16w+16) -> u in regs;
//                   candidate cols [16w,16w+16); own h (regs) + h update.
//   R-warps (8-15): reset gate cols [16(w-8), +16); reconstruct h from smem
//                   hi/lo, write rh into separate RH buffer.
// Separate H and RH buffers remove both WAR barriers; u never leaves regs.
// =============================================================================
#define BPB 16
#define THR 512
#define O_WGH 0
#define O_WGL 69632
#define O_WCH 139264
#define O_WCL 174080
#define O_HH  208896
#define O_HL  213248
#define O_RH  217600
#define O_RL  221952
#define REC_SMEM 226304

__global__ void __launch_bounds__(THR, 1) augru_recurrent_tc(
    const float* __restrict__ Gx, const float* __restrict__ Cx,
    const float* __restrict__ att,
    const int* __restrict__ perm, const int* __restrict__ sls,
    const __nv_bfloat16* __restrict__ WThi, const __nv_bfloat16* __restrict__ WTlo,
    const float* __restrict__ bg, const float* __restrict__ bc,
    float* __restrict__ out)
{
    extern __shared__ char smem[];
    const int tid = threadIdx.x;
    const int g0  = blockIdx.x * BPB;

    // ---- stage recurrent weights (h-part, k 128..255) as [col][272B] ----
    for (int i = tid; i < 256 * 16; i += THR) {
        int col = i >> 4, q = i & 15;
        *(uint4*)(smem + O_WGH + col * 272 + q * 16) = *(const uint4*)&WThi[(size_t)col * 256 + 128 + q * 8];
        *(uint4*)(smem + O_WGL + col * 272 + q * 16) = *(const uint4*)&WTlo[(size_t)col * 256 + 128 + q * 8];
    }
    for (int i = tid; i < 128 * 16; i += THR) {
        int col = i >> 4, q = i & 15;
        *(uint4*)(smem + O_WCH + col * 272 + q * 16) = *(const uint4*)&WThi[(size_t)(256 + col) * 256 + 128 + q * 8];
        *(uint4*)(smem + O_WCL + col * 272 + q * 16) = *(const uint4*)&WTlo[(size_t)(256 + col) * 256 + 128 + q * 8];
    }
    for (int i = tid; i < (4352 * 4) / 16; i += THR)    // zero H + RH (hi/lo)
        *(uint4*)(smem + O_HH + i * 16) = make_uint4(0, 0, 0, 0);

    const int wid = tid >> 5, lane = tid & 31;
    const int g = lane >> 2, tig = lane & 3;
    const bool isU = (wid < 8);
    const int cb  = isU ? wid * 16 : (wid - 8) * 16;   // owned h-col base
    const int gcb = isU ? 128 + cb : cb;               // gate-col base

    const int pb_lo = perm[g0 + g], pb_hi = perm[g0 + g + 8];
    const int sl_lo = sls[g0 + g],  sl_hi = sls[g0 + g + 8];
    const int maxsl = sls[g0];
    const size_t rb_lo = (size_t)pb_lo * T_, rb_hi = (size_t)pb_hi * T_;

    // biases
    float bgv[2][2], bcv[2][2];
#pragma unroll
    for (int nt = 0; nt < 2; nt++) {
        int cp = gcb + nt * 8 + 2 * tig;
        bgv[nt][0] = bg[cp]; bgv[nt][1] = bg[cp + 1];
        int cc = cb + nt * 8 + 2 * tig;
        bcv[nt][0] = isU ? bc[cc] : 0.0f;
        bcv[nt][1] = isU ? bc[cc + 1] : 0.0f;
    }

    // U-warp state: h registers (rows g / g+8, cols cb+nt*8+2tig, +1)
    float hreg[2][4];
#pragma unroll
    for (int nt = 0; nt < 2; nt++)
#pragma unroll
        for (int e = 0; e < 4; e++) hreg[nt][e] = 0.0f;

    // prefetch: all warps Gx at their gate cols; U also Cx + att
    float2 pG[2][2], pC[2][2];
    float patt0 = 0.f, patt1 = 0.f;
#pragma unroll
    for (int r = 0; r < 2; r++)
#pragma unroll
        for (int nt = 0; nt < 2; nt++) { pG[r][nt] = make_float2(0.f, 0.f); pC[r][nt] = make_float2(0.f, 0.f); }
    if (maxsl > 0) {
#pragma unroll
        for (int nt = 0; nt < 2; nt++) {
            int cp = gcb + nt * 8 + 2 * tig;
            pG[0][nt] = *(const float2*)&Gx[rb_lo * 256 + cp];
            pG[1][nt] = *(const float2*)&Gx[rb_hi * 256 + cp];
            if (isU) {
                int cc = cb + nt * 8 + 2 * tig;
                pC[0][nt] = *(const float2*)&Cx[rb_lo * 128 + cc];
                pC[1][nt] = *(const float2*)&Cx[rb_hi * 128 + cc];
            }
        }
        if (isU) { patt0 = att[rb_lo]; patt1 = att[rb_hi]; }
    }

    __syncthreads();   // weights + zeroed buffers visible

    float u[2][4];

    for (int t = 0; t < maxsl; t++) {
        const float2 cG0 = pG[0][0], cG1 = pG[1][0], cG2 = pG[0][1], cG3 = pG[1][1];
        const float2 cC0 = pC[0][0], cC1 = pC[1][0], cC2 = pC[0][1], cC3 = pC[1][1];
        const float at0 = patt0, at1 = patt1;

        if (t + 1 < maxsl) {
            const size_t n0 = rb_lo + t + 1, n1 = rb_hi + t + 1;
#pragma unroll
            for (int nt = 0; nt < 2; nt++) {
                int cp = gcb + nt * 8 + 2 * tig;
                pG[0][nt] = *(const float2*)&Gx[n0 * 256 + cp];
                pG[1][nt] = *(const float2*)&Gx[n1 * 256 + cp];
                if (isU) {
                    int cc = cb + nt * 8 + 2 * tig;
                    pC[0][nt] = *(const float2*)&Cx[n0 * 128 + cc];
                    pC[1][nt] = *(const float2*)&Cx[n1 * 128 + cc];
                }
            }
            if (isU) { patt0 = att[n0]; patt1 = att[n1]; }
        }
        const float2 gA[2][2] = {{cG0, cG2}, {cG1, cG3}};   // [row][nt]
        const float2 gC[2][2] = {{cC0, cC2}, {cC1, cC3}};

        // ---- gate MMAs: A = h (O_HH/O_HL), B = gate cols gcb.. ----
        float a0[2][4], a1[2][4];
#pragma unroll
        for (int nt = 0; nt < 2; nt++)
#pragma unroll
            for (int e = 0; e < 4; e++) { a0[nt][e] = 0.f; a1[nt][e] = 0.f; }

#pragma unroll
        for (int k0 = 0; k0 < 128; k0 += 16) {
            const int ka = k0 + 2 * tig;
            uint32_t ah0 = *(const uint32_t*)(smem + O_HH + g * 272 + ka * 2);
            uint32_t ah1 = *(const uint32_t*)(smem + O_HH + (g + 8) * 272 + ka * 2);
            uint32_t ah2 = *(const uint32_t*)(smem + O_HH + g * 272 + (ka + 8) * 2);
            uint32_t ah3 = *(const uint32_t*)(smem + O_HH + (g + 8) * 272 + (ka + 8) * 2);
            uint32_t al0 = *(const uint32_t*)(smem + O_HL + g * 272 + ka * 2);
            uint32_t al1 = *(const uint32_t*)(smem + O_HL + (g + 8) * 272 + ka * 2);
            uint32_t al2 = *(const uint32_t*)(smem + O_HL + g * 272 + (ka + 8) * 2);
            uint32_t al3 = *(const uint32_t*)(smem + O_HL + (g + 8) * 272 + (ka + 8) * 2);
#pragma unroll
            for (int nt = 0; nt < 2; nt++) {
                int col = gcb + nt * 8 + g;
                uint32_t bh0 = *(const uint32_t*)(smem + O_WGH + col * 272 + ka * 2);
                uint32_t bh1 = *(const uint32_t*)(smem + O_WGH + col * 272 + (ka + 8) * 2);
                uint32_t bl0 = *(const uint32_t*)(smem + O_WGL + col * 272 + ka * 2);
                uint32_t bl1 = *(const uint32_t*)(smem + O_WGL + col * 272 + (ka + 8) * 2);
                mma16816(a0[nt], ah0, ah1, ah2, ah3, bh0, bh1);
                mma16816(a1[nt], al0, al1, al2, al3, bh0, bh1);
                mma16816(a1[nt], ah0, ah1, ah2, ah3, bl0, bl1);
            }
        }

        // ---- epilogue 1 (no barrier before it) ----
        if (isU) {
            // update gate -> u registers
#pragma unroll
            for (int nt = 0; nt < 2; nt++) {
                u[nt][0] = at0 * sigmoid_fast(a0[nt][0] + a1[nt][0] + gA[0][nt].x + bgv[nt][0]);
                u[nt][1] = at0 * sigmoid_fast(a0[nt][1] + a1[nt][1] + gA[0][nt].y + bgv[nt][1]);
                u[nt][2] = at1 * sigmoid_fast(a0[nt][2] + a1[nt][2] + gA[1][nt].x + bgv[nt][0]);
                u[nt][3] = at1 * sigmoid_fast(a0[nt][3] + a1[nt][3] + gA[1][nt].y + bgv[nt][1]);
            }
        } else {
            // reset gate -> rh (reconstruct h from smem hi/lo) -> RH buffer
#pragma unroll
            for (int nt = 0; nt < 2; nt++) {
                int cp = cb + nt * 8 + 2 * tig;
                float r0 = sigmoid_fast(a0[nt][0] + a1[nt][0] + gA[0][nt].x + bgv[nt][0]);
                float r1 = sigmoid_fast(a0[nt][1] + a1[nt][1] + gA[0][nt].y + bgv[nt][1]);
                float r2 = sigmoid_fast(a0[nt][2] + a1[nt][2] + gA[1][nt].x + bgv[nt][0]);
                float r3 = sigmoid_fast(a0[nt][3] + a1[nt][3] + gA[1][nt].y + bgv[nt][1]);
                uint32_t hh_lo = *(const uint32_t*)(smem + O_HH + g * 272 + cp * 2);
                uint32_t hl_lo = *(const uint32_t*)(smem + O_HL + g * 272 + cp * 2);
                uint32_t hh_hi = *(const uint32_t*)(smem + O_HH + (g + 8) * 272 + cp * 2);
                uint32_t hl_hi = *(const uint32_t*)(smem + O_HL + (g + 8) * 272 + cp * 2);
                float rh0 = r0 * (bflo(hh_lo) + bflo(hl_lo));
                float rh1 = r1 * (bfhi(hh_lo) + bfhi(hl_lo));
                float rh2 = r2 * (bflo(hh_hi) + bflo(hl_hi));
                float rh3 = r3 * (bfhi(hh_hi) + bfhi(hl_hi));
                uint32_t p0 = bf16pack(rh0, rh1), p1 = bf16pack(rh2, rh3);
                *(uint32_t*)(smem + O_RH + g * 272 + cp * 2)       = p0;
                *(uint32_t*)(smem + O_RH + (g + 8) * 272 + cp * 2) = p1;
                *(uint32_t*)(smem + O_RL + g * 272 + cp * 2)       = bf16res(rh0, rh1, p0);
                *(uint32_t*)(smem + O_RL + (g + 8) * 272 + cp * 2) = bf16res(rh2, rh3, p1);
            }
        }
        __syncthreads();   // BARRIER A: rh visible; all h reads (gate) complete

        if (isU) {
            // ---- candidate MMAs: A = rh (O_RH/O_RL), B = cand cols cb.. ----
            float c0[2][4], c1[2][4];
#pragma unroll
            for (int nt = 0; nt < 2; nt++)
#pragma unroll
                for (int e = 0; e < 4; e++) { c0[nt][e] = 0.f; c1[nt][e] = 0.f; }
#pragma unroll
            for (int k0 = 0; k0 < 128; k0 += 16) {
                const int ka = k0 + 2 * tig;
                uint32_t ah0 = *(const uint32_t*)(smem + O_RH + g * 272 + ka * 2);
                uint32_t ah1 = *(const uint32_t*)(smem + O_RH + (g + 8) * 272 + ka * 2);
                uint32_t ah2 = *(const uint32_t*)(smem + O_RH + g * 272 + (ka + 8) * 2);
                uint32_t ah3 = *(const uint32_t*)(smem + O_RH + (g + 8) * 272 + (ka + 8) * 2);
                uint32_t al0 = *(const uint32_t*)(smem + O_RL + g * 272 + ka * 2);
                uint32_t al1 = *(const uint32_t*)(smem + O_RL + (g + 8) * 272 + ka * 2);
                uint32_t al2 = *(const uint32_t*)(smem + O_RL + g * 272 + (ka + 8) * 2);
                uint32_t al3 = *(const uint32_t*)(smem + O_RL + (g + 8) * 272 + (ka + 8) * 2);
#pragma unroll
                for (int nt = 0; nt < 2; nt++) {
                    int col = cb + nt * 8 + g;
                    uint32_t bh0 = *(const uint32_t*)(smem + O_WCH + col * 272 + ka * 2);
                    uint32_t bh1 = *(const uint32_t*)(smem + O_WCH + col * 272 + (ka + 8) * 2);
                    uint32_t bl0 = *(const uint32_t*)(smem + O_WCL + col * 272 + ka * 2);
                    uint32_t bl1 = *(const uint32_t*)(smem + O_WCL + col * 272 + (ka + 8) * 2);
                    mma16816(c0[nt], ah0, ah1, ah2, ah3, bh0, bh1);
                    mma16816(c1[nt], al0, al1, al2, al3, bh0, bh1);
                    mma16816(c1[nt], ah0, ah1, ah2, ah3, bl0, bl1);
                }
            }
            // ---- epilogue 2: h update + masked output + new h -> H buffer ----
            const bool v_lo = (t < sl_lo), v_hi = (t < sl_hi);
#pragma unroll
            for (int nt = 0; nt < 2; nt++) {
                int cp = cb + nt * 8 + 2 * tig;
                float cv0 = tanh_fast(c0[nt][0] + c1[nt][0] + gC[0][nt].x + bcv[nt][0]);
                float cv1 = tanh_fast(c0[nt][1] + c1[nt][1] + gC[0][nt].y + bcv[nt][1]);
                float cv2 = tanh_fast(c0[nt][2] + c1[nt][2] + gC[1][nt].x + bcv[nt][0]);
                float cv3 = tanh_fast(c0[nt][3] + c1[nt][3] + gC[1][nt].y + bcv[nt][1]);
                float hn0 = (1.0f - u[nt][0]) * hreg[nt][0] + u[nt][0] * cv0;
                float hn1 = (1.0f - u[nt][1]) * hreg[nt][1] + u[nt][1] * cv1;
                float hn2 = (1.0f - u[nt][2]) * hreg[nt][2] + u[nt][2] * cv2;
                float hn3 = (1.0f - u[nt][3]) * hreg[nt][3] + u[nt][3] * cv3;
                *(float2*)&out[(rb_lo + t) * 128 + cp] = v_lo ? make_float2(hn0, hn1)
                                                              : make_float2(0.f, 0.f);
                *(float2*)&out[(rb_hi + t) * 128 + cp] = v_hi ? make_float2(hn2, hn3)
                                                              : make_float2(0.f, 0.f);
                hreg[nt][0] = v_lo ? hn0 : hreg[nt][0];
                hreg[nt][1] = v_lo ? hn1 : hreg[nt][1];
                hreg[nt][2] = v_hi ? hn2 : hreg[nt][2];
                hreg[nt][3] = v_hi ? hn3 : hreg[nt][3];
                uint32_t p0 = bf16pack(hreg[nt][0], hreg[nt][1]);
                uint32_t p1 = bf16pack(hreg[nt][2], hreg[nt][3]);
                *(uint32_t*)(smem + O_HH + g * 272 + cp * 2)       = p0;
                *(uint32_t*)(smem + O_HH + (g + 8) * 272 + cp * 2) = p1;
                *(uint32_t*)(smem + O_HL + g * 272 + cp * 2)       = bf16res(hreg[nt][0], hreg[nt][1], p0);
                *(uint32_t*)(smem + O_HL + (g + 8) * 272 + cp * 2) = bf16res(hreg[nt][2], hreg[nt][3], p1);
            }
        }
        __syncthreads();   // BARRIER B: new h visible; rh reads complete
    }

    // ---- zero tail: t in [maxsl, T) for all 16 batches ----
    for (int idx = tid; idx < (T_ - maxsl) * BPB * 32; idx += THR) {
        int t  = maxsl + idx / (BPB * 32);
        int r  = idx % (BPB * 32);
        int i  = r >> 5;
        int j4 = (r & 31) << 2;
        int b  = perm[g0 + i];
        *(float4*)&out[((size_t)b * T_ + t) * 128 + j4] = make_float4(0.f, 0.f, 0.f, 0.f);
    }
}

// =============================================================================
extern "C" void kernel_launch(void* const* d_in, const int* in_sizes, int n_in,
                              void* d_out, int out_size)
{
    (void)in_sizes; (void)n_in; (void)out_size;
    const float* X      = (const float*)d_in[0];
    const float* att    = (const float*)d_in[1];
    const int*   seqlen = (const int*)  d_in[2];
    const float* Wg     = (const float*)d_in[3];
    const float* bg     = (const float*)d_in[4];
    const float* Wc     = (const float*)d_in[5];
    const float* bc     = (const float*)d_in[6];
    float* out          = (float*)d_out;

    float *Gx, *Cx; int *perm, *sls; __nv_bfloat16 *WThi, *WTlo;
    cudaGetSymbolAddress((void**)&Gx,   g_Gx);
    cudaGetSymbolAddress((void**)&Cx,   g_Cx);
    cudaGetSymbolAddress((void**)&perm, g_perm);
    cudaGetSymbolAddress((void**)&sls,  g_sls);
    cudaGetSymbolAddress((void**)&WThi, g_WThi);
    cudaGetSymbolAddress((void**)&WTlo, g_WTlo);

    augru_wprep<<<12, 256>>>(Wg, Wc, WThi, WTlo);
    augru_sort<<<B_ / 256, 256>>>(seqlen, perm, sls);

    cudaFuncSetAttribute(augru_precompute_mma,
                         cudaFuncAttributeMaxDynamicSharedMemorySize, PC_SMEM);
    augru_precompute_mma<<<M_ / 128, 256, PC_SMEM>>>(X, WThi, WTlo, seqlen, Gx, Cx);

    cudaFuncSetAttribute(augru_recurrent_tc,
                         cudaFuncAttributeMaxDynamicSharedMemorySize, REC_SMEM);
    augru_recurrent_tc<<<B_ / BPB, THR, REC_SMEM>>>(Gx, Cx, att, perm, sls,
                                                    WThi, WTlo, bg, bc, out);
}

// round 11
// speedup vs baseline: 1.4979x; 1.4979x over previous
#include <cuda_runtime.h>
#include <cuda_bf16.h>
#include <cstdint>

#define B_   2048
#define T_   200
#define D_   128
#define H_   128
#define M_   (B_ * T_)          // 409600 rows

// ---------------- scratch (static device arrays; no allocation) ----------------
__device__ float g_Gx[(size_t)M_ * 256];   // x-part of gate pre-activations (NO bias)
__device__ float g_Cx[(size_t)M_ * 128];   // x-part of candidate pre-activations (NO bias)
__device__ int   g_perm[B_];
__device__ int   g_sls[B_];
// Full W^T hi/lo: [n (384)][k (256)].  k 0..127 = x-part, 128..255 = h-part
__device__ __align__(16) __nv_bfloat16 g_WThi[384 * 256];
__device__ __align__(16) __nv_bfloat16 g_WTlo[384 * 256];

// ---------------- math helpers ---------------------------------------------------
__device__ __forceinline__ float sigmoid_fast(float x) {
    float e;
    asm("ex2.approx.f32 %0, %1;" : "=f"(e) : "f"(-1.4426950408889634f * x));
    float r;
    asm("rcp.approx.f32 %0, %1;" : "=f"(r) : "f"(1.0f + e));
    return r;
}
__device__ __forceinline__ float tanh_fast(float x) {
    return fmaf(2.0f, sigmoid_fast(2.0f * x), -1.0f);
}
__device__ __forceinline__ uint32_t bf16pack(float a, float b) {
    __nv_bfloat16 ha = __float2bfloat16(a), hb = __float2bfloat16(b);
    return ((uint32_t)__bfloat16_as_ushort(hb) << 16) | __bfloat16_as_ushort(ha);
}
__device__ __forceinline__ uint32_t smem_u32(const void* p) {
    uint32_t a;
    asm("{ .reg .u64 t; cvta.to.shared.u64 t, %1; cvt.u32.u64 %0, t; }" : "=r"(a) : "l"(p));
    return a;
}

// ---------------- warp-level bf16 MMA (sm_80+, legal on compute_103) -------------
__device__ __forceinline__ void mma16816(float* c,
    uint32_t a0, uint32_t a1, uint32_t a2, uint32_t a3,
    uint32_t b0, uint32_t b1)
{
    asm volatile(
        "mma.sync.aligned.m16n8k16.row.col.f32.bf16.bf16.f32 "
        "{%0,%1,%2,%3}, {%4,%5,%6,%7}, {%8,%9}, {%0,%1,%2,%3};"
        : "+f"(c[0]), "+f"(c[1]), "+f"(c[2]), "+f"(c[3])
        : "r"(a0), "r"(a1), "r"(a2), "r"(a3), "r"(b0), "r"(b1));
}
__device__ __forceinline__ void cpasync16(uint32_t dst, const void* src) {
    asm volatile("cp.async.cg.shared.global [%0], [%1], 16;" :: "r"(dst), "l"(src));
}
#define CPASYNC_COMMIT() asm volatile("cp.async.commit_group;" ::: "memory")
#define CPASYNC_WAIT(N)  asm volatile("cp.async.wait_group %0;" :: "n"(N) : "memory")

// =============================================================================
// Kernel 0a: FULL W transpose + bf16 hi/lo split. WT[n][k] = W[k][n], k 0..255.
// =============================================================================
__global__ void __launch_bounds__(256) augru_wprep(
    const float* __restrict__ Wg, const float* __restrict__ Wc,
    __nv_bfloat16* __restrict__ WThi, __nv_bfloat16* __restrict__ WTlo)
{
    __shared__ float s[32][33];
    const int n0 = blockIdx.x * 32;
    const int tx = threadIdx.x & 31, ty = threadIdx.x >> 5;
    for (int k0 = 0; k0 < 256; k0 += 32) {
        for (int rr = 0; rr < 32; rr += 8) {
            int k = k0 + ty + rr, n = n0 + tx;
            s[ty + rr][tx] = (n0 < 256) ? Wg[(size_t)k * 256 + n]
                                        : Wc[(size_t)k * 128 + (n - 256)];
        }
        __syncthreads();
        for (int rr = 0; rr < 32; rr += 8) {
            int n = n0 + ty + rr, k = k0 + tx;
            float v = s[tx][ty + rr];
            __nv_bfloat16 hi = __float2bfloat16(v);
            float lo = v - __bfloat162float(hi);
            WThi[(size_t)n * 256 + k] = hi;
            WTlo[(size_t)n * 256 + k] = __float2bfloat16(lo);
        }
        __syncthreads();
    }
}

// =============================================================================
// Kernel 0b: parallel deterministic sort by seq_len, DESCENDING.
// =============================================================================
__global__ void __launch_bounds__(256) augru_sort(const int* __restrict__ seqlen,
                                                  int* __restrict__ perm,
                                                  int* __restrict__ sls)
{
    __shared__ int sl[B_];
    const int tid = threadIdx.x;
    for (int i = tid; i < B_; i += 256) sl[i] = seqlen[i];
    __syncthreads();
    const int b = blockIdx.x * 256 + tid;
    const int v = sl[b];
    int pos = 0;
#pragma unroll 8
    for (int j = 0; j < B_; j++) {
        int u = sl[j];
        pos += (u > v) || (u == v && j < b);
    }
    perm[pos] = b;
    sls[pos]  = v;
}

// =============================================================================
// Kernel 1: merged HMMA precompute (R9/R10 version — X staged once, W double-
// buffered via cp.async overlapping MMA). Verified −77 µs vs split version.
// =============================================================================
#define BSTR 136
#define QA_H 0
#define QA_L 34816
#define QB0  69632
#define QB1  139264
#define PC_SMEM 208896

__global__ void __launch_bounds__(256, 1) augru_precompute_mma(
    const float* __restrict__ X,
    const __nv_bfloat16* __restrict__ WThi,
    const __nv_bfloat16* __restrict__ WTlo,
    const int* __restrict__ seqlen,
    float* __restrict__ Gx, float* __restrict__ Cx)
{
    const int m0 = blockIdx.x * 128;
    {
        int b1 = m0 / T_;
        int t1 = m0 - b1 * T_;
        bool any = (t1 < seqlen[b1]);
        int b2 = (m0 + 127) / T_;
        if (b2 != b1) any = any || (seqlen[b2] > 0);
        if (!any) return;
    }

    extern __shared__ char smem[];
    const uint32_t sb = smem_u32(smem);
    const int tid = threadIdx.x;

    auto issueB = [&](int nt, uint32_t bufo) {
#pragma unroll
        for (int q = 0; q < 8; q++) {
            int f = q * 256 + tid;
            int n = f >> 4, c = f & 15;
            cpasync16(sb + bufo + n * 272 + c * 16,
                      &WThi[(size_t)(nt * 128 + n) * 256 + c * 8]);
        }
#pragma unroll
        for (int q = 0; q < 8; q++) {
            int f = q * 256 + tid;
            int n = f >> 4, c = f & 15;
            cpasync16(sb + bufo + 34816 + n * 272 + c * 16,
                      &WTlo[(size_t)(nt * 128 + n) * 256 + c * 8]);
        }
        CPASYNC_COMMIT();
    };

    issueB(0, QB0);

#pragma unroll
    for (int q = 0; q < 16; q++) {
        int f = q * 256 + tid;
        int m = f >> 5, k = (f & 31) << 2;
        float4 v = *(const float4*)&X[(size_t)(m0 + m) * 128 + k];
        __nv_bfloat16 h0 = __float2bfloat16(v.x), h1 = __float2bfloat16(v.y);
        __nv_bfloat16 h2 = __float2bfloat16(v.z), h3 = __float2bfloat16(v.w);
        uint32_t hv0 = ((uint32_t)__bfloat16_as_ushort(h1) << 16) | __bfloat16_as_ushort(h0);
        uint32_t hv1 = ((uint32_t)__bfloat16_as_ushort(h3) << 16) | __bfloat16_as_ushort(h2);
        uint32_t lv0 = bf16pack(v.x - __bfloat162float(h0), v.y - __bfloat162float(h1));
        uint32_t lv1 = bf16pack(v.z - __bfloat162float(h2), v.w - __bfloat162float(h3));
        size_t o = ((size_t)m * BSTR + k) * 2;
        *(uint32_t*)(smem + QA_H + o)     = hv0;
        *(uint32_t*)(smem + QA_H + o + 4) = hv1;
        *(uint32_t*)(smem + QA_L + o)     = lv0;
        *(uint32_t*)(smem + QA_L + o + 4) = lv1;
    }

    issueB(1, QB1);

    const int wid = tid >> 5, lane = tid & 31;
    const int wm = wid >> 2, wn = wid & 3;
    const int g = lane >> 2, tig = lane & 3;

    auto mmaNT = [&](int nt, uint32_t bufo) {
        float acc[4][4][4];
#pragma unroll
        for (int i = 0; i < 4; i++)
#pragma unroll
            for (int j = 0; j < 4; j++)
#pragma unroll
                for (int e = 0; e < 4; e++) acc[i][j][e] = 0.0f;

        const char* Bh = smem + bufo;
        const char* Bl = smem + bufo + 34816;
#pragma unroll 1
        for (int prod = 0; prod < 3; prod++) {
            const char* Ab = smem + ((prod == 1) ? QA_L : QA_H);
            const char* Bb = (prod == 2) ? Bl : Bh;
#pragma unroll
            for (int ks = 0; ks < 8; ks++) {
                const int k0 = ks * 16 + 2 * tig;
                uint32_t a[4][4], b[4][2];
#pragma unroll
                for (int ma = 0; ma < 4; ma++) {
                    int r0 = wm * 64 + ma * 16 + g;
                    a[ma][0] = *(const uint32_t*)(Ab + ((size_t)r0 * BSTR + k0) * 2);
                    a[ma][1] = *(const uint32_t*)(Ab + ((size_t)(r0 + 8) * BSTR + k0) * 2);
                    a[ma][2] = *(const uint32_t*)(Ab + ((size_t)r0 * BSTR + k0 + 8) * 2);
                    a[ma][3] = *(const uint32_t*)(Ab + ((size_t)(r0 + 8) * BSTR + k0 + 8) * 2);
                }
#pragma unroll
                for (int na = 0; na < 4; na++) {
                    int n0 = wn * 32 + na * 8 + g;
                    b[na][0] = *(const uint32_t*)(Bb + ((size_t)n0 * BSTR + k0) * 2);
                    b[na][1] = *(const uint32_t*)(Bb + ((size_t)n0 * BSTR + k0 + 8) * 2);
                }
#pragma unroll
                for (int ma = 0; ma < 4; ma++)
#pragma unroll
                    for (int na = 0; na < 4; na++)
                        mma16816(acc[ma][na], a[ma][0], a[ma][1], a[ma][2], a[ma][3],
                                 b[na][0], b[na][1]);
            }
        }
        float* Out = (nt < 2) ? Gx : Cx;
        const int ldo = (nt < 2) ? 256 : 128;
        const int nc0 = (nt < 2) ? nt * 128 : 0;
#pragma unroll
        for (int ma = 0; ma < 4; ma++) {
            int r = m0 + wm * 64 + ma * 16 + g;
#pragma unroll
            for (int na = 0; na < 4; na++) {
                int col = nc0 + wn * 32 + na * 8 + 2 * tig;
                *(float2*)&Out[(size_t)r * ldo + col] = make_float2(acc[ma][na][0], acc[ma][na][1]);
                *(float2*)&Out[(size_t)(r + 8) * ldo + col] = make_float2(acc[ma][na][2], acc[ma][na][3]);
            }
        }
    };

    CPASYNC_WAIT(1);
    __syncthreads();
    mmaNT(0, QB0);
    __syncthreads();
    issueB(2, QB0);
    CPASYNC_WAIT(1);
    __syncthreads();
    mmaNT(1, QB1);
    CPASYNC_WAIT(0);
    __syncthreads();
    mmaNT(2, QB0);
}

// =============================================================================
// Kernel 2: HMMA recurrence — EXACT R8 structure (699 us measured).
// BPB=16 sorted batches/block, 128 blocks (1 wave), 512 threads (16 warps).
// All weights bf16 hi/lo [col][k] in smem (stride 136, conflict-free).
// h state in registers of warps 0-7; uu through smem; 4 barriers/step.
// =============================================================================
#define BPB 16
#define THR 512
#define O_WGH 0
#define O_WGL 69632
#define O_WCH 139264
#define O_WCL 174080
#define O_AH  208896
#define O_AL  213248
#define O_UU  217600
#define REC_SMEM 226048    // O_UU + 16*132*4

__global__ void __launch_bounds__(THR, 1) augru_recurrent_tc(
    const float* __restrict__ Gx, const float* __restrict__ Cx,
    const float* __restrict__ att,
    const int* __restrict__ perm, const int* __restrict__ sls,
    const __nv_bfloat16* __restrict__ WThi, const __nv_bfloat16* __restrict__ WTlo,
    const float* __restrict__ bg, const float* __restrict__ bc,
    float* __restrict__ out)
{
    extern __shared__ char smem[];
    const int tid = threadIdx.x;
    const int g0  = blockIdx.x * BPB;

    // ---- stage recurrent weights (h-part, k 128..255) as [col][272B] bf16 ----
    for (int i = tid; i < 256 * 16; i += THR) {
        int col = i >> 4, q = (i & 15);
        *(uint4*)(smem + O_WGH + col * 272 + q * 16) = *(const uint4*)&WThi[(size_t)col * 256 + 128 + q * 8];
        *(uint4*)(smem + O_WGL + col * 272 + q * 16) = *(const uint4*)&WTlo[(size_t)col * 256 + 128 + q * 8];
    }
    for (int i = tid; i < 128 * 16; i += THR) {
        int col = i >> 4, q = (i & 15);
        *(uint4*)(smem + O_WCH + col * 272 + q * 16) = *(const uint4*)&WThi[(size_t)(256 + col) * 256 + 128 + q * 8];
        *(uint4*)(smem + O_WCL + col * 272 + q * 16) = *(const uint4*)&WTlo[(size_t)(256 + col) * 256 + 128 + q * 8];
    }
    // zero A buffers (h = 0)
    for (int i = tid; i < (4352 * 2) / 16; i += THR)
        *(uint4*)(smem + O_AH + i * 16) = make_uint4(0, 0, 0, 0);

    const int wid = tid >> 5, lane = tid & 31;
    const int g = lane >> 2, tig = lane & 3;
    const int nbase = wid * 16;                 // gate cols [nbase, nbase+16)
    const bool lowW = (wid < 8);
    const int ucol = nbase - 128;               // update-col base (warps 8-15)

    const int pb_lo = perm[g0 + g], pb_hi = perm[g0 + g + 8];
    const int sl_lo = sls[g0 + g],  sl_hi = sls[g0 + g + 8];
    const int maxsl = sls[g0];
    const size_t rb_lo = (size_t)pb_lo * T_, rb_hi = (size_t)pb_hi * T_;

    // biases (per-lane constants)
    float bgv[2][2], bcv2[2][2];
#pragma unroll
    for (int nt = 0; nt < 2; nt++) {
        int cp = nbase + nt * 8 + 2 * tig;   // 0..255 gate col
        bgv[nt][0] = bg[cp]; bgv[nt][1] = bg[cp + 1];
        if (lowW) { bcv2[nt][0] = bc[cp]; bcv2[nt][1] = bc[cp + 1]; }
        else      { bcv2[nt][0] = bcv2[nt][1] = 0.0f; }
    }

    // h state registers (warps 0-7): h[nt][e], e: 0=(g,c),1=(g,c+1),2=(g+8,c),3=(g+8,c+1)
    float hreg[2][4];
#pragma unroll
    for (int nt = 0; nt < 2; nt++)
#pragma unroll
        for (int e = 0; e < 4; e++) hreg[nt][e] = 0.0f;

    // prefetch buffers: warps 0-7: pA = Gx reset pairs, pB = Cx pairs
    //                   warps 8-15: pA = Gx update pairs, att
    float2 pA[2][2], pB[2][2];                  // [row(lo/hi)][nt]
    float patt_lo = 0.0f, patt_hi = 0.0f;
#pragma unroll
    for (int r = 0; r < 2; r++)
#pragma unroll
        for (int nt = 0; nt < 2; nt++) { pA[r][nt] = make_float2(0.f, 0.f); pB[r][nt] = make_float2(0.f, 0.f); }
    if (maxsl > 0) {
#pragma unroll
        for (int nt = 0; nt < 2; nt++) {
            int cp = nbase + nt * 8 + 2 * tig;   // gate col (0..255)
            pA[0][nt] = *(const float2*)&Gx[rb_lo * 256 + cp];
            pA[1][nt] = *(const float2*)&Gx[rb_hi * 256 + cp];
            if (lowW) {
                pB[0][nt] = *(const float2*)&Cx[rb_lo * 128 + cp];
                pB[1][nt] = *(const float2*)&Cx[rb_hi * 128 + cp];
            }
        }
        if (!lowW) { patt_lo = att[rb_lo]; patt_hi = att[rb_hi]; }
    }

    __syncthreads();   // weights + A zero visible

    for (int t = 0; t < maxsl; t++) {
        // consume this step's prefetched values
        float2 cA[2][2], cB[2][2];
        float att_lo = patt_lo, att_hi = patt_hi;
#pragma unroll
        for (int r = 0; r < 2; r++)
#pragma unroll
            for (int nt = 0; nt < 2; nt++) { cA[r][nt] = pA[r][nt]; cB[r][nt] = pB[r][nt]; }

        // issue t+1 prefetch (overlaps gate MMAs)
        if (t + 1 < maxsl) {
            const size_t n_lo = rb_lo + t + 1, n_hi = rb_hi + t + 1;
#pragma unroll
            for (int nt = 0; nt < 2; nt++) {
                int cp = nbase + nt * 8 + 2 * tig;
                pA[0][nt] = *(const float2*)&Gx[n_lo * 256 + cp];
                pA[1][nt] = *(const float2*)&Gx[n_hi * 256 + cp];
                if (lowW) {
                    pB[0][nt] = *(const float2*)&Cx[n_lo * 128 + cp];
                    pB[1][nt] = *(const float2*)&Cx[n_hi * 128 + cp];
                }
            }
            if (!lowW) { patt_lo = att[n_lo]; patt_hi = att[n_hi]; }
        }

        // ---- gate MMAs: all warps, cols [nbase, nbase+16), A = h hi/lo ----
        float acc[2][4];
#pragma unroll
        for (int nt = 0; nt < 2; nt++)
#pragma unroll
            for (int e = 0; e < 4; e++) acc[nt][e] = 0.0f;

#pragma unroll
        for (int k0 = 0; k0 < 128; k0 += 16) {
            const int ka = k0 + 2 * tig;
            uint32_t ah0 = *(const uint32_t*)(smem + O_AH + g * 272 + ka * 2);
            uint32_t ah1 = *(const uint32_t*)(smem + O_AH + (g + 8) * 272 + ka * 2);
            uint32_t ah2 = *(const uint32_t*)(smem + O_AH + g * 272 + (ka + 8) * 2);
            uint32_t ah3 = *(const uint32_t*)(smem + O_AH + (g + 8) * 272 + (ka + 8) * 2);
            uint32_t al0 = *(const uint32_t*)(smem + O_AL + g * 272 + ka * 2);
            uint32_t al1 = *(const uint32_t*)(smem + O_AL + (g + 8) * 272 + ka * 2);
            uint32_t al2 = *(const uint32_t*)(smem + O_AL + g * 272 + (ka + 8) * 2);
            uint32_t al3 = *(const uint32_t*)(smem + O_AL + (g + 8) * 272 + (ka + 8) * 2);
#pragma unroll
            for (int nt = 0; nt < 2; nt++) {
                int col = nbase + nt * 8 + g;
                uint32_t bh0 = *(const uint32_t*)(smem + O_WGH + col * 272 + ka * 2);
                uint32_t bh1 = *(const uint32_t*)(smem + O_WGH + col * 272 + (ka + 8) * 2);
                uint32_t bl0 = *(const uint32_t*)(smem + O_WGL + col * 272 + ka * 2);
                uint32_t bl1 = *(const uint32_t*)(smem + O_WGL + col * 272 + (ka + 8) * 2);
                mma16816(acc[nt], ah0, ah1, ah2, ah3, bh0, bh1);
                mma16816(acc[nt], al0, al1, al2, al3, bh0, bh1);
                mma16816(acc[nt], ah0, ah1, ah2, ah3, bl0, bl1);
            }
        }
        __syncthreads();   // all gate reads of A done

        // ---- gate epilogue ----
        if (lowW) {
            // reset gate -> rh = r * h  -> A buffer (bf16 hi/lo)
#pragma unroll
            for (int nt = 0; nt < 2; nt++) {
                int cp = nbase + nt * 8 + 2 * tig;
                float r00 = sigmoid_fast(acc[nt][0] + cA[0][nt].x + bgv[nt][0]);
                float r01 = sigmoid_fast(acc[nt][1] + cA[0][nt].y + bgv[nt][1]);
                float r10 = sigmoid_fast(acc[nt][2] + cA[1][nt].x + bgv[nt][0]);
                float r11 = sigmoid_fast(acc[nt][3] + cA[1][nt].y + bgv[nt][1]);
                float rh00 = r00 * hreg[nt][0], rh01 = r01 * hreg[nt][1];
                float rh10 = r10 * hreg[nt][2], rh11 = r11 * hreg[nt][3];
                uint32_t hi0 = bf16pack(rh00, rh01);
                uint32_t hi1 = bf16pack(rh10, rh11);
                float l00 = rh00 - __bfloat162float(__ushort_as_bfloat16((unsigned short)(hi0 & 0xFFFF)));
                float l01 = rh01 - __bfloat162float(__ushort_as_bfloat16((unsigned short)(hi0 >> 16)));
                float l10 = rh10 - __bfloat162float(__ushort_as_bfloat16((unsigned short)(hi1 & 0xFFFF)));
                float l11 = rh11 - __bfloat162float(__ushort_as_bfloat16((unsigned short)(hi1 >> 16)));
                *(uint32_t*)(smem + O_AH + g * 272 + cp * 2)       = hi0;
                *(uint32_t*)(smem + O_AH + (g + 8) * 272 + cp * 2) = hi1;
                *(uint32_t*)(smem + O_AL + g * 272 + cp * 2)       = bf16pack(l00, l01);
                *(uint32_t*)(smem + O_AL + (g + 8) * 272 + cp * 2) = bf16pack(l10, l11);
            }
        } else {
            // update gate -> u = att * sigmoid -> UU (fp32)
#pragma unroll
            for (int nt = 0; nt < 2; nt++) {
                int cp = ucol + nt * 8 + 2 * tig;
                float u00 = att_lo * sigmoid_fast(acc[nt][0] + cA[0][nt].x + bgv[nt][0]);
                float u01 = att_lo * sigmoid_fast(acc[nt][1] + cA[0][nt].y + bgv[nt][1]);
                float u10 = att_hi * sigmoid_fast(acc[nt][2] + cA[1][nt].x + bgv[nt][0]);
                float u11 = att_hi * sigmoid_fast(acc[nt][3] + cA[1][nt].y + bgv[nt][1]);
                *(float2*)(smem + O_UU + (g * 132 + cp) * 4)       = make_float2(u00, u01);
                *(float2*)(smem + O_UU + ((g + 8) * 132 + cp) * 4) = make_float2(u10, u11);
            }
        }
        __syncthreads();   // rh + uu ready

        // ---- candidate MMAs: warps 0-7, cols [nbase, nbase+16), A = rh ----
        if (lowW) {
#pragma unroll
            for (int nt = 0; nt < 2; nt++)
#pragma unroll
                for (int e = 0; e < 4; e++) acc[nt][e] = 0.0f;
#pragma unroll
            for (int k0 = 0; k0 < 128; k0 += 16) {
                const int ka = k0 + 2 * tig;
                uint32_t ah0 = *(const uint32_t*)(smem + O_AH + g * 272 + ka * 2);
                uint32_t ah1 = *(const uint32_t*)(smem + O_AH + (g + 8) * 272 + ka * 2);
                uint32_t ah2 = *(const uint32_t*)(smem + O_AH + g * 272 + (ka + 8) * 2);
                uint32_t ah3 = *(const uint32_t*)(smem + O_AH + (g + 8) * 272 + (ka + 8) * 2);
                uint32_t al0 = *(const uint32_t*)(smem + O_AL + g * 272 + ka * 2);
                uint32_t al1 = *(const uint32_t*)(smem + O_AL + (g + 8) * 272 + ka * 2);
                uint32_t al2 = *(const uint32_t*)(smem + O_AL + g * 272 + (ka + 8) * 2);
                uint32_t al3 = *(const uint32_t*)(smem + O_AL + (g + 8) * 272 + (ka + 8) * 2);
#pragma unroll
                for (int nt = 0; nt < 2; nt++) {
                    int col = nbase + nt * 8 + g;
                    uint32_t bh0 = *(const uint32_t*)(smem + O_WCH + col * 272 + ka * 2);
                    uint32_t bh1 = *(const uint32_t*)(smem + O_WCH + col * 272 + (ka + 8) * 2);
                    uint32_t bl0 = *(const uint32_t*)(smem + O_WCL + col * 272 + ka * 2);
                    uint32_t bl1 = *(const uint32_t*)(smem + O_WCL + col * 272 + (ka + 8) * 2);
                    mma16816(acc[nt], ah0, ah1, ah2, ah3, bh0, bh1);
                    mma16816(acc[nt], al0, al1, al2, al3, bh0, bh1);
                    mma16816(acc[nt], ah0, ah1, ah2, ah3, bl0, bl1);
                }
            }
        }
        __syncthreads();   // candidate reads of A (rh) done

        // ---- candidate epilogue: h update + masked output + new h -> A ----
        if (lowW) {
            const bool v_lo = (t < sl_lo), v_hi = (t < sl_hi);
#pragma unroll
            for (int nt = 0; nt < 2; nt++) {
                int cp = nbase + nt * 8 + 2 * tig;
                float c00 = tanh_fast(acc[nt][0] + cB[0][nt].x + bcv2[nt][0]);
                float c01 = tanh_fast(acc[nt][1] + cB[0][nt].y + bcv2[nt][1]);
                float c10 = tanh_fast(acc[nt][2] + cB[1][nt].x + bcv2[nt][0]);
                float c11 = tanh_fast(acc[nt][3] + cB[1][nt].y + bcv2[nt][1]);
                float2 u_lo = *(const float2*)(smem + O_UU + (g * 132 + cp) * 4);
                float2 u_hi = *(const float2*)(smem + O_UU + ((g + 8) * 132 + cp) * 4);
                float hn00 = (1.0f - u_lo.x) * hreg[nt][0] + u_lo.x * c00;
                float hn01 = (1.0f - u_lo.y) * hreg[nt][1] + u_lo.y * c01;
                float hn10 = (1.0f - u_hi.x) * hreg[nt][2] + u_hi.x * c10;
                float hn11 = (1.0f - u_hi.y) * hreg[nt][3] + u_hi.y * c11;
                *(float2*)&out[(rb_lo + t) * 128 + cp] = v_lo ? make_float2(hn00, hn01)
                                                              : make_float2(0.f, 0.f);
                *(float2*)&out[(rb_hi + t) * 128 + cp] = v_hi ? make_float2(hn10, hn11)
                                                              : make_float2(0.f, 0.f);
                hreg[nt][0] = v_lo ? hn00 : hreg[nt][0];
                hreg[nt][1] = v_lo ? hn01 : hreg[nt][1];
                hreg[nt][2] = v_hi ? hn10 : hreg[nt][2];
                hreg[nt][3] = v_hi ? hn11 : hreg[nt][3];
                // write new h (bf16 hi/lo) into A for next step's gate
                uint32_t hi0 = bf16pack(hreg[nt][0], hreg[nt][1]);
                uint32_t hi1 = bf16pack(hreg[nt][2], hreg[nt][3]);
                float l00 = hreg[nt][0] - __bfloat162float(__ushort_as_bfloat16((unsigned short)(hi0 & 0xFFFF)));
                float l01 = hreg[nt][1] - __bfloat162float(__ushort_as_bfloat16((unsigned short)(hi0 >> 16)));
                float l10 = hreg[nt][2] - __bfloat162float(__ushort_as_bfloat16((unsigned short)(hi1 & 0xFFFF)));
                float l11 = hreg[nt][3] - __bfloat162float(__ushort_as_bfloat16((unsigned short)(hi1 >> 16)));
                *(uint32_t*)(smem + O_AH + g * 272 + cp * 2)       = hi0;
                *(uint32_t*)(smem + O_AH + (g + 8) * 272 + cp * 2) = hi1;
                *(uint32_t*)(smem + O_AL + g * 272 + cp * 2)       = bf16pack(l00, l01);
                *(uint32_t*)(smem + O_AL + (g + 8) * 272 + cp * 2) = bf16pack(l10, l11);
            }
        }
        __syncthreads();   // new h visible to all warps' next gate MMAs
    }

    // ---- zero tail: t in [maxsl, T) for all 16 batches ----
    for (int idx = tid; idx < (T_ - maxsl) * BPB * 32; idx += THR) {
        int t  = maxsl + idx / (BPB * 32);
        int r  = idx % (BPB * 32);
        int i  = r >> 5;
        int j4 = (r & 31) << 2;
        int b  = perm[g0 + i];
        *(float4*)&out[((size_t)b * T_ + t) * 128 + j4] = make_float4(0.f, 0.f, 0.f, 0.f);
    }
}

// =============================================================================
extern "C" void kernel_launch(void* const* d_in, const int* in_sizes, int n_in,
                              void* d_out, int out_size)
{
    (void)in_sizes; (void)n_in; (void)out_size;
    const float* X      = (const float*)d_in[0];
    const float* att    = (const float*)d_in[1];
    const int*   seqlen = (const int*)  d_in[2];
    const float* Wg     = (const float*)d_in[3];
    const float* bg     = (const float*)d_in[4];
    const float* Wc     = (const float*)d_in[5];
    const float* bc     = (const float*)d_in[6];
    float* out          = (float*)d_out;

    float *Gx, *Cx; int *perm, *sls; __nv_bfloat16 *WThi, *WTlo;
    cudaGetSymbolAddress((void**)&Gx,   g_Gx);
    cudaGetSymbolAddress((void**)&Cx,   g_Cx);
    cudaGetSymbolAddress((void**)&perm, g_perm);
    cudaGetSymbolAddress((void**)&sls,  g_sls);
    cudaGetSymbolAddress((void**)&WThi, g_WThi);
    cudaGetSymbolAddress((void**)&WTlo, g_WTlo);

    augru_wprep<<<12, 256>>>(Wg, Wc, WThi, WTlo);
    augru_sort<<<B_ / 256, 256>>>(seqlen, perm, sls);

    cudaFuncSetAttribute(augru_precompute_mma,
                         cudaFuncAttributeMaxDynamicSharedMemorySize, PC_SMEM);
    augru_precompute_mma<<<M_ / 128, 256, PC_SMEM>>>(X, WThi, WTlo, seqlen, Gx, Cx);

    cudaFuncSetAttribute(augru_recurrent_tc,
                         cudaFuncAttributeMaxDynamicSharedMemorySize, REC_SMEM);
    augru_recurrent_tc<<<B_ / BPB, THR, REC_SMEM>>>(Gx, Cx, att, perm, sls,
                                                    WThi, WTlo, bg, bc, out);
}

// round 12
// speedup vs baseline: 1.5396x; 1.0278x over previous
#include <cuda_runtime.h>
#include <cuda_bf16.h>
#include <cstdint>

#define B_   2048
#define T_   200
#define D_   128
#define H_   128
#define M_   (B_ * T_)          // 409600 rows

// ---------------- scratch (static device arrays; no allocation) ----------------
__device__ float g_Gx[(size_t)M_ * 256];   // x-part of gate pre-activations (NO bias)
__device__ float g_Cx[(size_t)M_ * 128];   // x-part of candidate pre-activations (NO bias)
__device__ int   g_perm[B_];
__device__ int   g_sls[B_];
// Full W^T hi/lo: [n (384)][k (256)].  k 0..127 = x-part, 128..255 = h-part
__device__ __align__(16) __nv_bfloat16 g_WThi[384 * 256];
__device__ __align__(16) __nv_bfloat16 g_WTlo[384 * 256];

// ---------------- math helpers ---------------------------------------------------
__device__ __forceinline__ float sigmoid_fast(float x) {
    float e;
    asm("ex2.approx.f32 %0, %1;" : "=f"(e) : "f"(-1.4426950408889634f * x));
    float r;
    asm("rcp.approx.f32 %0, %1;" : "=f"(r) : "f"(1.0f + e));
    return r;
}
__device__ __forceinline__ float tanh_fast(float x) {
    return fmaf(2.0f, sigmoid_fast(2.0f * x), -1.0f);
}
__device__ __forceinline__ uint32_t bf16pack(float a, float b) {
    __nv_bfloat16 ha = __float2bfloat16(a), hb = __float2bfloat16(b);
    return ((uint32_t)__bfloat16_as_ushort(hb) << 16) | __bfloat16_as_ushort(ha);
}
__device__ __forceinline__ uint32_t smem_u32(const void* p) {
    uint32_t a;
    asm("{ .reg .u64 t; cvta.to.shared.u64 t, %1; cvt.u32.u64 %0, t; }" : "=r"(a) : "l"(p));
    return a;
}

// ---------------- warp-level bf16 MMA + ldmatrix (sm_75/80+, legal) --------------
__device__ __forceinline__ void mma16816(float* c,
    uint32_t a0, uint32_t a1, uint32_t a2, uint32_t a3,
    uint32_t b0, uint32_t b1)
{
    asm volatile(
        "mma.sync.aligned.m16n8k16.row.col.f32.bf16.bf16.f32 "
        "{%0,%1,%2,%3}, {%4,%5,%6,%7}, {%8,%9}, {%0,%1,%2,%3};"
        : "+f"(c[0]), "+f"(c[1]), "+f"(c[2]), "+f"(c[3])
        : "r"(a0), "r"(a1), "r"(a2), "r"(a3), "r"(b0), "r"(b1));
}
__device__ __forceinline__ void ldsm_x4(uint32_t& r0, uint32_t& r1, uint32_t& r2,
                                        uint32_t& r3, uint32_t addr) {
    asm volatile("ldmatrix.sync.aligned.m8n8.x4.shared.b16 {%0,%1,%2,%3}, [%4];"
                 : "=r"(r0), "=r"(r1), "=r"(r2), "=r"(r3) : "r"(addr));
}
__device__ __forceinline__ void cpasync16(uint32_t dst, const void* src) {
    asm volatile("cp.async.cg.shared.global [%0], [%1], 16;" :: "r"(dst), "l"(src));
}
#define CPASYNC_COMMIT() asm volatile("cp.async.commit_group;" ::: "memory")
#define CPASYNC_WAIT(N)  asm volatile("cp.async.wait_group %0;" :: "n"(N) : "memory")

// =============================================================================
// Kernel 0a: FULL W transpose + bf16 hi/lo split. WT[n][k] = W[k][n], k 0..255.
// =============================================================================
__global__ void __launch_bounds__(256) augru_wprep(
    const float* __restrict__ Wg, const float* __restrict__ Wc,
    __nv_bfloat16* __restrict__ WThi, __nv_bfloat16* __restrict__ WTlo)
{
    __shared__ float s[32][33];
    const int n0 = blockIdx.x * 32;
    const int tx = threadIdx.x & 31, ty = threadIdx.x >> 5;
    for (int k0 = 0; k0 < 256; k0 += 32) {
        for (int rr = 0; rr < 32; rr += 8) {
            int k = k0 + ty + rr, n = n0 + tx;
            s[ty + rr][tx] = (n0 < 256) ? Wg[(size_t)k * 256 + n]
                                        : Wc[(size_t)k * 128 + (n - 256)];
        }
        __syncthreads();
        for (int rr = 0; rr < 32; rr += 8) {
            int n = n0 + ty + rr, k = k0 + tx;
            float v = s[tx][ty + rr];
            __nv_bfloat16 hi = __float2bfloat16(v);
            float lo = v - __bfloat162float(hi);
            WThi[(size_t)n * 256 + k] = hi;
            WTlo[(size_t)n * 256 + k] = __float2bfloat16(lo);
        }
        __syncthreads();
    }
}

// =============================================================================
// Kernel 0b: parallel deterministic sort by seq_len, DESCENDING.
// =============================================================================
__global__ void __launch_bounds__(256) augru_sort(const int* __restrict__ seqlen,
                                                  int* __restrict__ perm,
                                                  int* __restrict__ sls)
{
    __shared__ int sl[B_];
    const int tid = threadIdx.x;
    for (int i = tid; i < B_; i += 256) sl[i] = seqlen[i];
    __syncthreads();
    const int b = blockIdx.x * 256 + tid;
    const int v = sl[b];
    int pos = 0;
#pragma unroll 8
    for (int j = 0; j < B_; j++) {
        int u = sl[j];
        pos += (u > v) || (u == v && j < b);
    }
    perm[pos] = b;
    sls[pos]  = v;
}

// =============================================================================
// Kernel 1: merged HMMA precompute (R9/R10 version, verified win — unchanged).
// =============================================================================
#define BSTR 136
#define QA_H 0
#define QA_L 34816
#define QB0  69632
#define QB1  139264
#define PC_SMEM 208896

__global__ void __launch_bounds__(256, 1) augru_precompute_mma(
    const float* __restrict__ X,
    const __nv_bfloat16* __restrict__ WThi,
    const __nv_bfloat16* __restrict__ WTlo,
    const int* __restrict__ seqlen,
    float* __restrict__ Gx, float* __restrict__ Cx)
{
    const int m0 = blockIdx.x * 128;
    {
        int b1 = m0 / T_;
        int t1 = m0 - b1 * T_;
        bool any = (t1 < seqlen[b1]);
        int b2 = (m0 + 127) / T_;
        if (b2 != b1) any = any || (seqlen[b2] > 0);
        if (!any) return;
    }

    extern __shared__ char smem[];
    const uint32_t sb = smem_u32(smem);
    const int tid = threadIdx.x;

    auto issueB = [&](int nt, uint32_t bufo) {
#pragma unroll
        for (int q = 0; q < 8; q++) {
            int f = q * 256 + tid;
            int n = f >> 4, c = f & 15;
            cpasync16(sb + bufo + n * 272 + c * 16,
                      &WThi[(size_t)(nt * 128 + n) * 256 + c * 8]);
        }
#pragma unroll
        for (int q = 0; q < 8; q++) {
            int f = q * 256 + tid;
            int n = f >> 4, c = f & 15;
            cpasync16(sb + bufo + 34816 + n * 272 + c * 16,
                      &WTlo[(size_t)(nt * 128 + n) * 256 + c * 8]);
        }
        CPASYNC_COMMIT();
    };

    issueB(0, QB0);

#pragma unroll
    for (int q = 0; q < 16; q++) {
        int f = q * 256 + tid;
        int m = f >> 5, k = (f & 31) << 2;
        float4 v = *(const float4*)&X[(size_t)(m0 + m) * 128 + k];
        __nv_bfloat16 h0 = __float2bfloat16(v.x), h1 = __float2bfloat16(v.y);
        __nv_bfloat16 h2 = __float2bfloat16(v.z), h3 = __float2bfloat16(v.w);
        uint32_t hv0 = ((uint32_t)__bfloat16_as_ushort(h1) << 16) | __bfloat16_as_ushort(h0);
        uint32_t hv1 = ((uint32_t)__bfloat16_as_ushort(h3) << 16) | __bfloat16_as_ushort(h2);
        uint32_t lv0 = bf16pack(v.x - __bfloat162float(h0), v.y - __bfloat162float(h1));
        uint32_t lv1 = bf16pack(v.z - __bfloat162float(h2), v.w - __bfloat162float(h3));
        size_t o = ((size_t)m * BSTR + k) * 2;
        *(uint32_t*)(smem + QA_H + o)     = hv0;
        *(uint32_t*)(smem + QA_H + o + 4) = hv1;
        *(uint32_t*)(smem + QA_L + o)     = lv0;
        *(uint32_t*)(smem + QA_L + o + 4) = lv1;
    }

    issueB(1, QB1);

    const int wid = tid >> 5, lane = tid & 31;
    const int wm = wid >> 2, wn = wid & 3;
    const int g = lane >> 2, tig = lane & 3;

    auto mmaNT = [&](int nt, uint32_t bufo) {
        float acc[4][4][4];
#pragma unroll
        for (int i = 0; i < 4; i++)
#pragma unroll
            for (int j = 0; j < 4; j++)
#pragma unroll
                for (int e = 0; e < 4; e++) acc[i][j][e] = 0.0f;

        const char* Bh = smem + bufo;
        const char* Bl = smem + bufo + 34816;
#pragma unroll 1
        for (int prod = 0; prod < 3; prod++) {
            const char* Ab = smem + ((prod == 1) ? QA_L : QA_H);
            const char* Bb = (prod == 2) ? Bl : Bh;
#pragma unroll
            for (int ks = 0; ks < 8; ks++) {
                const int k0 = ks * 16 + 2 * tig;
                uint32_t a[4][4], b[4][2];
#pragma unroll
                for (int ma = 0; ma < 4; ma++) {
                    int r0 = wm * 64 + ma * 16 + g;
                    a[ma][0] = *(const uint32_t*)(Ab + ((size_t)r0 * BSTR + k0) * 2);
                    a[ma][1] = *(const uint32_t*)(Ab + ((size_t)(r0 + 8) * BSTR + k0) * 2);
                    a[ma][2] = *(const uint32_t*)(Ab + ((size_t)r0 * BSTR + k0 + 8) * 2);
                    a[ma][3] = *(const uint32_t*)(Ab + ((size_t)(r0 + 8) * BSTR + k0 + 8) * 2);
                }
#pragma unroll
                for (int na = 0; na < 4; na++) {
                    int n0 = wn * 32 + na * 8 + g;
                    b[na][0] = *(const uint32_t*)(Bb + ((size_t)n0 * BSTR + k0) * 2);
                    b[na][1] = *(const uint32_t*)(Bb + ((size_t)n0 * BSTR + k0 + 8) * 2);
                }
#pragma unroll
                for (int ma = 0; ma < 4; ma++)
#pragma unroll
                    for (int na = 0; na < 4; na++)
                        mma16816(acc[ma][na], a[ma][0], a[ma][1], a[ma][2], a[ma][3],
                                 b[na][0], b[na][1]);
            }
        }
        float* Out = (nt < 2) ? Gx : Cx;
        const int ldo = (nt < 2) ? 256 : 128;
        const int nc0 = (nt < 2) ? nt * 128 : 0;
#pragma unroll
        for (int ma = 0; ma < 4; ma++) {
            int r = m0 + wm * 64 + ma * 16 + g;
#pragma unroll
            for (int na = 0; na < 4; na++) {
                int col = nc0 + wn * 32 + na * 8 + 2 * tig;
                *(float2*)&Out[(size_t)r * ldo + col] = make_float2(acc[ma][na][0], acc[ma][na][1]);
                *(float2*)&Out[(size_t)(r + 8) * ldo + col] = make_float2(acc[ma][na][2], acc[ma][na][3]);
            }
        }
    };

    CPASYNC_WAIT(1);
    __syncthreads();
    mmaNT(0, QB0);
    __syncthreads();
    issueB(2, QB0);
    CPASYNC_WAIT(1);
    __syncthreads();
    mmaNT(1, QB1);
    CPASYNC_WAIT(0);
    __syncthreads();
    mmaNT(2, QB0);
}

// =============================================================================
// Kernel 2: HMMA recurrence — R8 structure (699 us), SINGLE CHANGE: all
// fragment loads via ldmatrix.x4 (mixed-buffer tiles: one x4 = {Whi k0,
// Whi k0+8, Wlo k0, Wlo k0+8}). Mapping/barriers/epilogues identical to R8.
// =============================================================================
#define BPB 16
#define THR 512
#define O_WGH 0
#define O_WGL 69632
#define O_WCH 139264
#define O_WCL 174080
#define O_AH  208896
#define O_AL  213248
#define O_UU  217600
#define REC_SMEM 226048    // O_UU + 16*132*4

__global__ void __launch_bounds__(THR, 1) augru_recurrent_tc(
    const float* __restrict__ Gx, const float* __restrict__ Cx,
    const float* __restrict__ att,
    const int* __restrict__ perm, const int* __restrict__ sls,
    const __nv_bfloat16* __restrict__ WThi, const __nv_bfloat16* __restrict__ WTlo,
    const float* __restrict__ bg, const float* __restrict__ bc,
    float* __restrict__ out)
{
    extern __shared__ char smem[];
    const uint32_t sb = smem_u32(smem);
    const int tid = threadIdx.x;
    const int g0  = blockIdx.x * BPB;

    // ---- stage recurrent weights (h-part, k 128..255) as [col][272B] bf16 ----
    for (int i = tid; i < 256 * 16; i += THR) {
        int col = i >> 4, q = (i & 15);
        *(uint4*)(smem + O_WGH + col * 272 + q * 16) = *(const uint4*)&WThi[(size_t)col * 256 + 128 + q * 8];
        *(uint4*)(smem + O_WGL + col * 272 + q * 16) = *(const uint4*)&WTlo[(size_t)col * 256 + 128 + q * 8];
    }
    for (int i = tid; i < 128 * 16; i += THR) {
        int col = i >> 4, q = (i & 15);
        *(uint4*)(smem + O_WCH + col * 272 + q * 16) = *(const uint4*)&WThi[(size_t)(256 + col) * 256 + 128 + q * 8];
        *(uint4*)(smem + O_WCL + col * 272 + q * 16) = *(const uint4*)&WTlo[(size_t)(256 + col) * 256 + 128 + q * 8];
    }
    // zero A buffers (h = 0)
    for (int i = tid; i < (4352 * 2) / 16; i += THR)
        *(uint4*)(smem + O_AH + i * 16) = make_uint4(0, 0, 0, 0);

    const int wid = tid >> 5, lane = tid & 31;
    const int g = lane >> 2, tig = lane & 3;
    const int nbase = wid * 16;                 // gate cols [nbase, nbase+16)
    const bool lowW = (wid < 8);
    const int ucol = nbase - 128;               // update-col base (warps 8-15)

    // ---- ldmatrix lane-group addresses ----
    const int am = lane >> 3;                   // group id 0..3
    // A tiles: m0=(r0-7,k0) m1=(r8-15,k0) m2=(r0-7,k0+8) m3=(r8-15,k0+8)
    const uint32_t aoff = (uint32_t)(((am & 1) * 8 + (lane & 7)) * 272 + ((am >> 1) * 8) * 2);
    const uint32_t aAhi = sb + O_AH + aoff;
    const uint32_t aAlo = sb + O_AL + aoff;
    // gate/cand B tiles: m0=(hi,k0) m1=(hi,k0+8) m2=(lo,k0) m3=(lo,k0+8)
    const uint32_t bk   = (uint32_t)(((am & 1) * 8) * 2);          // k-offset bytes
    const uint32_t bcol = (uint32_t)((nbase + (lane & 7)) * 272);  // col*272 (nt=0)
    const uint32_t gB0  = sb + ((am >> 1) ? O_WGL : O_WGH) + bcol + bk;   // gate nt=0
    const uint32_t gB1  = gB0 + 8 * 272;                                   // gate nt=1
    const uint32_t cB0  = sb + ((am >> 1) ? O_WCL : O_WCH) + bcol + bk;   // cand nt=0 (lowW)
    const uint32_t cB1  = cB0 + 8 * 272;

    const int pb_lo = perm[g0 + g], pb_hi = perm[g0 + g + 8];
    const int sl_lo = sls[g0 + g],  sl_hi = sls[g0 + g + 8];
    const int maxsl = sls[g0];
    const size_t rb_lo = (size_t)pb_lo * T_, rb_hi = (size_t)pb_hi * T_;

    // biases (per-lane constants)
    float bgv[2][2], bcv2[2][2];
#pragma unroll
    for (int nt = 0; nt < 2; nt++) {
        int cp = nbase + nt * 8 + 2 * tig;   // 0..255 gate col
        bgv[nt][0] = bg[cp]; bgv[nt][1] = bg[cp + 1];
        if (lowW) { bcv2[nt][0] = bc[cp]; bcv2[nt][1] = bc[cp + 1]; }
        else      { bcv2[nt][0] = bcv2[nt][1] = 0.0f; }
    }

    // h state registers (warps 0-7)
    float hreg[2][4];
#pragma unroll
    for (int nt = 0; nt < 2; nt++)
#pragma unroll
        for (int e = 0; e < 4; e++) hreg[nt][e] = 0.0f;

    // prefetch buffers
    float2 pA[2][2], pB[2][2];                  // [row(lo/hi)][nt]
    float patt_lo = 0.0f, patt_hi = 0.0f;
#pragma unroll
    for (int r = 0; r < 2; r++)
#pragma unroll
        for (int nt = 0; nt < 2; nt++) { pA[r][nt] = make_float2(0.f, 0.f); pB[r][nt] = make_float2(0.f, 0.f); }
    if (maxsl > 0) {
#pragma unroll
        for (int nt = 0; nt < 2; nt++) {
            int cp = nbase + nt * 8 + 2 * tig;
            pA[0][nt] = *(const float2*)&Gx[rb_lo * 256 + cp];
            pA[1][nt] = *(const float2*)&Gx[rb_hi * 256 + cp];
            if (lowW) {
                pB[0][nt] = *(const float2*)&Cx[rb_lo * 128 + cp];
                pB[1][nt] = *(const float2*)&Cx[rb_hi * 128 + cp];
            }
        }
        if (!lowW) { patt_lo = att[rb_lo]; patt_hi = att[rb_hi]; }
    }

    __syncthreads();   // weights + A zero visible

    for (int t = 0; t < maxsl; t++) {
        float2 cA[2][2], cB[2][2];
        float att_lo = patt_lo, att_hi = patt_hi;
#pragma unroll
        for (int r = 0; r < 2; r++)
#pragma unroll
            for (int nt = 0; nt < 2; nt++) { cA[r][nt] = pA[r][nt]; cB[r][nt] = pB[r][nt]; }

        if (t + 1 < maxsl) {
            const size_t n_lo = rb_lo + t + 1, n_hi = rb_hi + t + 1;
#pragma unroll
            for (int nt = 0; nt < 2; nt++) {
                int cp = nbase + nt * 8 + 2 * tig;
                pA[0][nt] = *(const float2*)&Gx[n_lo * 256 + cp];
                pA[1][nt] = *(const float2*)&Gx[n_hi * 256 + cp];
                if (lowW) {
                    pB[0][nt] = *(const float2*)&Cx[n_lo * 128 + cp];
                    pB[1][nt] = *(const float2*)&Cx[n_hi * 128 + cp];
                }
            }
            if (!lowW) { patt_lo = att[n_lo]; patt_hi = att[n_hi]; }
        }

        // ---- gate MMAs (ldmatrix fragments) ----
        float acc[2][4];
#pragma unroll
        for (int nt = 0; nt < 2; nt++)
#pragma unroll
            for (int e = 0; e < 4; e++) acc[nt][e] = 0.0f;

#pragma unroll
        for (int k0 = 0; k0 < 128; k0 += 16) {
            uint32_t ah0, ah1, ah2, ah3, al0, al1, al2, al3;
            ldsm_x4(ah0, ah1, ah2, ah3, aAhi + k0 * 2);
            ldsm_x4(al0, al1, al2, al3, aAlo + k0 * 2);
            uint32_t b00, b01, b02, b03, b10, b11, b12, b13;
            ldsm_x4(b00, b01, b02, b03, gB0 + k0 * 2);   // {Whi k0, Whi k0+8, Wlo k0, Wlo k0+8}
            ldsm_x4(b10, b11, b12, b13, gB1 + k0 * 2);
            mma16816(acc[0], ah0, ah1, ah2, ah3, b00, b01);
            mma16816(acc[0], al0, al1, al2, al3, b00, b01);
            mma16816(acc[0], ah0, ah1, ah2, ah3, b02, b03);
            mma16816(acc[1], ah0, ah1, ah2, ah3, b10, b11);
            mma16816(acc[1], al0, al1, al2, al3, b10, b11);
            mma16816(acc[1], ah0, ah1, ah2, ah3, b12, b13);
        }
        __syncthreads();   // all gate reads of A done

        // ---- gate epilogue (identical to R8) ----
        if (lowW) {
#pragma unroll
            for (int nt = 0; nt < 2; nt++) {
                int cp = nbase + nt * 8 + 2 * tig;
                float r00 = sigmoid_fast(acc[nt][0] + cA[0][nt].x + bgv[nt][0]);
                float r01 = sigmoid_fast(acc[nt][1] + cA[0][nt].y + bgv[nt][1]);
                float r10 = sigmoid_fast(acc[nt][2] + cA[1][nt].x + bgv[nt][0]);
                float r11 = sigmoid_fast(acc[nt][3] + cA[1][nt].y + bgv[nt][1]);
                float rh00 = r00 * hreg[nt][0], rh01 = r01 * hreg[nt][1];
                float rh10 = r10 * hreg[nt][2], rh11 = r11 * hreg[nt][3];
                uint32_t hi0 = bf16pack(rh00, rh01);
                uint32_t hi1 = bf16pack(rh10, rh11);
                float l00 = rh00 - __bfloat162float(__ushort_as_bfloat16((unsigned short)(hi0 & 0xFFFF)));
                float l01 = rh01 - __bfloat162float(__ushort_as_bfloat16((unsigned short)(hi0 >> 16)));
                float l10 = rh10 - __bfloat162float(__ushort_as_bfloat16((unsigned short)(hi1 & 0xFFFF)));
                float l11 = rh11 - __bfloat162float(__ushort_as_bfloat16((unsigned short)(hi1 >> 16)));
                *(uint32_t*)(smem + O_AH + g * 272 + cp * 2)       = hi0;
                *(uint32_t*)(smem + O_AH + (g + 8) * 272 + cp * 2) = hi1;
                *(uint32_t*)(smem + O_AL + g * 272 + cp * 2)       = bf16pack(l00, l01);
                *(uint32_t*)(smem + O_AL + (g + 8) * 272 + cp * 2) = bf16pack(l10, l11);
            }
        } else {
#pragma unroll
            for (int nt = 0; nt < 2; nt++) {
                int cp = ucol + nt * 8 + 2 * tig;
                float u00 = att_lo * sigmoid_fast(acc[nt][0] + cA[0][nt].x + bgv[nt][0]);
                float u01 = att_lo * sigmoid_fast(acc[nt][1] + cA[0][nt].y + bgv[nt][1]);
                float u10 = att_hi * sigmoid_fast(acc[nt][2] + cA[1][nt].x + bgv[nt][0]);
                float u11 = att_hi * sigmoid_fast(acc[nt][3] + cA[1][nt].y + bgv[nt][1]);
                *(float2*)(smem + O_UU + (g * 132 + cp) * 4)       = make_float2(u00, u01);
                *(float2*)(smem + O_UU + ((g + 8) * 132 + cp) * 4) = make_float2(u10, u11);
            }
        }
        __syncthreads();   // rh + uu ready

        // ---- candidate MMAs: warps 0-7 (ldmatrix fragments) ----
        if (lowW) {
#pragma unroll
            for (int nt = 0; nt < 2; nt++)
#pragma unroll
                for (int e = 0; e < 4; e++) acc[nt][e] = 0.0f;
#pragma unroll
            for (int k0 = 0; k0 < 128; k0 += 16) {
                uint32_t ah0, ah1, ah2, ah3, al0, al1, al2, al3;
                ldsm_x4(ah0, ah1, ah2, ah3, aAhi + k0 * 2);
                ldsm_x4(al0, al1, al2, al3, aAlo + k0 * 2);
                uint32_t b00, b01, b02, b03, b10, b11, b12, b13;
                ldsm_x4(b00, b01, b02, b03, cB0 + k0 * 2);
                ldsm_x4(b10, b11, b12, b13, cB1 + k0 * 2);
                mma16816(acc[0], ah0, ah1, ah2, ah3, b00, b01);
                mma16816(acc[0], al0, al1, al2, al3, b00, b01);
                mma16816(acc[0], ah0, ah1, ah2, ah3, b02, b03);
                mma16816(acc[1], ah0, ah1, ah2, ah3, b10, b11);
                mma16816(acc[1], al0, al1, al2, al3, b10, b11);
                mma16816(acc[1], ah0, ah1, ah2, ah3, b12, b13);
            }
        }
        __syncthreads();   // candidate reads of A (rh) done

        // ---- candidate epilogue (identical to R8) ----
        if (lowW) {
            const bool v_lo = (t < sl_lo), v_hi = (t < sl_hi);
#pragma unroll
            for (int nt = 0; nt < 2; nt++) {
                int cp = nbase + nt * 8 + 2 * tig;
                float c00 = tanh_fast(acc[nt][0] + cB[0][nt].x + bcv2[nt][0]);
                float c01 = tanh_fast(acc[nt][1] + cB[0][nt].y + bcv2[nt][1]);
                float c10 = tanh_fast(acc[nt][2] + cB[1][nt].x + bcv2[nt][0]);
                float c11 = tanh_fast(acc[nt][3] + cB[1][nt].y + bcv2[nt][1]);
                float2 u_lo = *(const float2*)(smem + O_UU + (g * 132 + cp) * 4);
                float2 u_hi = *(const float2*)(smem + O_UU + ((g + 8) * 132 + cp) * 4);
                float hn00 = (1.0f - u_lo.x) * hreg[nt][0] + u_lo.x * c00;
                float hn01 = (1.0f - u_lo.y) * hreg[nt][1] + u_lo.y * c01;
                float hn10 = (1.0f - u_hi.x) * hreg[nt][2] + u_hi.x * c10;
                float hn11 = (1.0f - u_hi.y) * hreg[nt][3] + u_hi.y * c11;
                *(float2*)&out[(rb_lo + t) * 128 + cp] = v_lo ? make_float2(hn00, hn01)
                                                              : make_float2(0.f, 0.f);
                *(float2*)&out[(rb_hi + t) * 128 + cp] = v_hi ? make_float2(hn10, hn11)
                                                              : make_float2(0.f, 0.f);
                hreg[nt][0] = v_lo ? hn00 : hreg[nt][0];
                hreg[nt][1] = v_lo ? hn01 : hreg[nt][1];
                hreg[nt][2] = v_hi ? hn10 : hreg[nt][2];
                hreg[nt][3] = v_hi ? hn11 : hreg[nt][3];
                uint32_t hi0 = bf16pack(hreg[nt][0], hreg[nt][1]);
                uint32_t hi1 = bf16pack(hreg[nt][2], hreg[nt][3]);
                float l00 = hreg[nt][0] - __bfloat162float(__ushort_as_bfloat16((unsigned short)(hi0 & 0xFFFF)));
                float l01 = hreg[nt][1] - __bfloat162float(__ushort_as_bfloat16((unsigned short)(hi0 >> 16)));
                float l10 = hreg[nt][2] - __bfloat162float(__ushort_as_bfloat16((unsigned short)(hi1 & 0xFFFF)));
                float l11 = hreg[nt][3] - __bfloat162float(__ushort_as_bfloat16((unsigned short)(hi1 >> 16)));
                *(uint32_t*)(smem + O_AH + g * 272 + cp * 2)       = hi0;
                *(uint32_t*)(smem + O_AH + (g + 8) * 272 + cp * 2) = hi1;
                *(uint32_t*)(smem + O_AL + g * 272 + cp * 2)       = bf16pack(l00, l01);
                *(uint32_t*)(smem + O_AL + (g + 8) * 272 + cp * 2) = bf16pack(l10, l11);
            }
        }
        __syncthreads();   // new h visible to all warps' next gate MMAs
    }

    // ---- zero tail: t in [maxsl, T) for all 16 batches ----
    for (int idx = tid; idx < (T_ - maxsl) * BPB * 32; idx += THR) {
        int t  = maxsl + idx / (BPB * 32);
        int r  = idx % (BPB * 32);
        int i  = r >> 5;
        int j4 = (r & 31) << 2;
        int b  = perm[g0 + i];
        *(float4*)&out[((size_t)b * T_ + t) * 128 + j4] = make_float4(0.f, 0.f, 0.f, 0.f);
    }
}

// =============================================================================
extern "C" void kernel_launch(void* const* d_in, const int* in_sizes, int n_in,
                              void* d_out, int out_size)
{
    (void)in_sizes; (void)n_in; (void)out_size;
    const float* X      = (const float*)d_in[0];
    const float* att    = (const float*)d_in[1];
    const int*   seqlen = (const int*)  d_in[2];
    const float* Wg     = (const float*)d_in[3];
    const float* bg     = (const float*)d_in[4];
    const float* Wc     = (const float*)d_in[5];
    const float* bc     = (const float*)d_in[6];
    float* out          = (float*)d_out;

    float *Gx, *Cx; int *perm, *sls; __nv_bfloat16 *WThi, *WTlo;
    cudaGetSymbolAddress((void**)&Gx,   g_Gx);
    cudaGetSymbolAddress((void**)&Cx,   g_Cx);
    cudaGetSymbolAddress((void**)&perm, g_perm);
    cudaGetSymbolAddress((void**)&sls,  g_sls);
    cudaGetSymbolAddress((void**)&WThi, g_WThi);
    cudaGetSymbolAddress((void**)&WTlo, g_WTlo);

    augru_wprep<<<12, 256>>>(Wg, Wc, WThi, WTlo);
    augru_sort<<<B_ / 256, 256>>>(seqlen, perm, sls);

    cudaFuncSetAttribute(augru_precompute_mma,
                         cudaFuncAttributeMaxDynamicSharedMemorySize, PC_SMEM);
    augru_precompute_mma<<<M_ / 128, 256, PC_SMEM>>>(X, WThi, WTlo, seqlen, Gx, Cx);

    cudaFuncSetAttribute(augru_recurrent_tc,
                         cudaFuncAttributeMaxDynamicSharedMemorySize, REC_SMEM);
    augru_recurrent_tc<<<B_ / BPB, THR, REC_SMEM>>>(Gx, Cx, att, perm, sls,
                                                    WThi, WTlo, bg, bc, out);
}